// round 8
// baseline (speedup 1.0000x reference)
#include <cuda_runtime.h>
#include <cstdint>

// Fixed problem shape: N=320000, C=64, B=4, NY=496, NX=432, NZ=1
#define NY_   496
#define NX_   432
#define C_    64
#define B_    4
#define NCELL (B_ * NY_ * NX_)        // 857,088 cells

#define RPB    2                      // y-rows per block
#define CELLS  (RPB * NX_)            // 864 cells per block
#define CCH    8                      // channels per chunk (8 chunks)
#define PITCH  868                    // SMEM pitch (864+4, multiple of 4)
#define THREADS_G 512

// Winner encoding: 0 = empty, w = point_index + 1.
// __device__ globals are zero-initialized at module load; the gather kernel
// re-zeroes each block's winner segment after consuming it, so the array is
// all-zero at every kernel_launch entry (identical state -> deterministic).
__device__ int4 g_winner4[NCELL / 4];

// ---------------------------------------------------------------------------
// Kernel 1: atomicMax scatter of (point index + 1). Last-write-wins == max.
// coors rows: (b, z, y, x), z == 0 always (NZ=1).
// ---------------------------------------------------------------------------
__global__ void scatter_winner_kernel(const int* __restrict__ coors, int n) {
    int i = blockIdx.x * blockDim.x + threadIdx.x;
    if (i < n) {
        int4 cz = *reinterpret_cast<const int4*>(coors + 4 * i);
        int cell = (cz.x * NY_ + cz.z) * NX_ + cz.w;
        atomicMax(reinterpret_cast<int*>(g_winner4) + cell, i + 1);
    }
}

// ---------------------------------------------------------------------------
// Kernel 2: one block per (b, y-pair) — 864 contiguous cells x 64 channels,
// processed in 8 chunks of 8 channels through a transposed SMEM tile.
//   Phase 0: 864 winners -> SMEM (216 int4), then reset them to 0 in GMEM.
//   Phase 2 (per chunk): strided over cells; read 32 B feature slice
//       (2x LDG.128), transpose-store 8 scalars (stride-1 STS).
//   Phase 3 (per chunk): 8 channels x 3456 B contiguous each,
//       LDS.128 + STG.128 fully coalesced.
// Static SMEM: 864*4 + 8*868*4 = 31,232 B (< 48 KB static cap).
// ---------------------------------------------------------------------------
__global__ __launch_bounds__(THREADS_G) void gather_pair_kernel(
    const float* __restrict__ feat, float* __restrict__ out) {

    __shared__ int   sw[CELLS];            // 3.4 KB
    __shared__ float tile[CCH * PITCH];    // 27.8 KB

    int t = threadIdx.x;
    int p = blockIdx.x;                    // 0 .. B*NY/RPB - 1  (992)
    int cell0 = p * CELLS;                 // contiguous winner segment

    // Phase 0: copy winners to SMEM, then zero them for the next replay.
    if (t < CELLS / 4) {
        int4 w4 = g_winner4[cell0 / 4 + t];
        *reinterpret_cast<int4*>(sw + 4 * t) = w4;
        g_winner4[cell0 / 4 + t] = make_int4(0, 0, 0, 0);
    }
    __syncthreads();

    int b  = p / (NY_ / RPB);
    int y0 = (p % (NY_ / RPB)) * RPB;
    size_t rowbase = ((size_t)(b * C_) * NY_ + y0) * NX_;

    #pragma unroll
    for (int cc = 0; cc < C_; cc += CCH) {
        // Phase 2: gather + transpose 8-channel slice for 864 cells
        for (int j = t; j < CELLS; j += THREADS_G) {
            int w = sw[j];
            float4 v0 = make_float4(0.f, 0.f, 0.f, 0.f);
            float4 v1 = v0;
            if (w > 0) {
                const float4* src = reinterpret_cast<const float4*>(
                    feat + (size_t)(w - 1) * C_ + cc);
                v0 = src[0]; v1 = src[1];
            }
            tile[0 * PITCH + j] = v0.x;  tile[1 * PITCH + j] = v0.y;
            tile[2 * PITCH + j] = v0.z;  tile[3 * PITCH + j] = v0.w;
            tile[4 * PITCH + j] = v1.x;  tile[5 * PITCH + j] = v1.y;
            tile[6 * PITCH + j] = v1.z;  tile[7 * PITCH + j] = v1.w;
        }
        __syncthreads();

        // Phase 3: 8 channels * 216 float4 = 1728 vector stores.
        // Per channel: 864 floats contiguous (rows y0, y0+1 adjoin).
        for (int q = t; q < CCH * (CELLS / 4); q += THREADS_G) {
            int k = q / (CELLS / 4);
            int g = q - k * (CELLS / 4);
            float4 v = *reinterpret_cast<const float4*>(&tile[k * PITCH + g * 4]);
            *reinterpret_cast<float4*>(
                out + rowbase + (size_t)(cc + k) * (NY_ * NX_) + g * 4) = v;
        }
        __syncthreads();
    }
}

// ---------------------------------------------------------------------------
extern "C" void kernel_launch(void* const* d_in, const int* in_sizes, int n_in,
                              void* d_out, int out_size) {
    const float* feat  = (const float*)d_in[0];   // [N, 64] float32
    const int*   coors = (const int*)d_in[1];     // [N, 4] int32
    (void)n_in; (void)out_size;

    int n = in_sizes[1] / 4;

    {   // 1) atomicMax (point index + 1); winner array is all-zero on entry
        int threads = 256;
        int blocks  = (n + threads - 1) / threads;
        scatter_winner_kernel<<<blocks, threads>>>(coors, n);
    }
    {   // 2) pair gather + transpose (+ winner reset for next replay)
        int blocks = B_ * NY_ / RPB;   // 992
        gather_pair_kernel<<<blocks, THREADS_G>>>(feat, (float*)d_out);
    }
}